// round 1
// baseline (speedup 1.0000x reference)
#include <cuda_runtime.h>
#include <math_constants.h>

#define BS 32
#define NQ 256
#define NT 128
#define NC 2048
#define BT (BS * NT)                  // 4096
#define CSIZE ((size_t)BS * NQ * BT)  // 33554432

// ---------------------------------------------------------------------------
// Kernel 1: masked softmax over classes + gather into cost matrix C = -prob
// One block per (b, q) row. 256 threads.
// ---------------------------------------------------------------------------
__global__ __launch_bounds__(256) void k_softmax_gather(
    const float* __restrict__ logits,   // [BS*NQ, NC]
    const int*   __restrict__ tgt,      // [BT]
    const int*   __restrict__ mask,     // [BS*NQ] (0/1)
    const int*   __restrict__ useBg,    // [1]
    float*       __restrict__ out)      // [BS*NQ, BT]
{
    __shared__ float sh[NC];     // exp values -> probs
    __shared__ int   st[BT];     // target ids
    __shared__ float red[8];

    const int row = blockIdx.x;
    const int tid = threadIdx.x;
    const int lane = tid & 31;
    const int warp = tid >> 5;

    const bool active = (useBg[0] != 0) || (mask[row] != 0);
    float* orow = out + (size_t)row * BT;

    if (!active) {
        const float4 z = make_float4(-0.0f, -0.0f, -0.0f, -0.0f);
        float4* o4 = (float4*)orow;
        #pragma unroll
        for (int j = tid; j < BT / 4; j += 256) o4[j] = z;
        return;
    }

    // cache target ids
    {
        const int4* tg4 = (const int4*)tgt;
        int4* st4 = (int4*)st;
        for (int j = tid; j < BT / 4; j += 256) st4[j] = tg4[j];
    }

    const float4* l4 = (const float4*)(logits + (size_t)row * NC);
    float4 v0 = l4[tid];
    float4 v1 = l4[tid + 256];

    // ---- max reduce ----
    float m = fmaxf(fmaxf(fmaxf(v0.x, v0.y), fmaxf(v0.z, v0.w)),
                    fmaxf(fmaxf(v1.x, v1.y), fmaxf(v1.z, v1.w)));
    #pragma unroll
    for (int o = 16; o; o >>= 1) m = fmaxf(m, __shfl_xor_sync(0xffffffffu, m, o));
    if (lane == 0) red[warp] = m;
    __syncthreads();
    if (tid == 0) {
        float t = red[0];
        #pragma unroll
        for (int w = 1; w < 8; w++) t = fmaxf(t, red[w]);
        red[0] = t;
    }
    __syncthreads();
    m = red[0];
    __syncthreads();

    // ---- exp + sum reduce ----
    float4 e0, e1;
    e0.x = expf(v0.x - m); e0.y = expf(v0.y - m);
    e0.z = expf(v0.z - m); e0.w = expf(v0.w - m);
    e1.x = expf(v1.x - m); e1.y = expf(v1.y - m);
    e1.z = expf(v1.z - m); e1.w = expf(v1.w - m);
    float s = (e0.x + e0.y) + (e0.z + e0.w) + (e1.x + e1.y) + (e1.z + e1.w);
    #pragma unroll
    for (int o = 16; o; o >>= 1) s += __shfl_xor_sync(0xffffffffu, s, o);
    if (lane == 0) red[warp] = s;
    __syncthreads();
    if (tid == 0) {
        float t = red[0];
        #pragma unroll
        for (int w = 1; w < 8; w++) t += red[w];
        red[0] = t;
    }
    __syncthreads();
    const float S = red[0];

    // normalize (exact division, like jax softmax) and store probs
    float4 p0, p1;
    p0.x = e0.x / S; p0.y = e0.y / S; p0.z = e0.z / S; p0.w = e0.w / S;
    p1.x = e1.x / S; p1.y = e1.y / S; p1.z = e1.z / S; p1.w = e1.w / S;
    ((float4*)sh)[tid]       = p0;
    ((float4*)sh)[tid + 256] = p1;
    __syncthreads();

    // ---- gather: C[row][j] = -probs[tgt[j]] ----
    float4* o4 = (float4*)orow;
    const int4* st4 = (const int4*)st;
    #pragma unroll
    for (int j = tid; j < BT / 4; j += 256) {
        int4 id = st4[j];
        float4 o;
        o.x = -sh[id.x];
        o.y = -sh[id.y];
        o.z = -sh[id.z];
        o.w = -sh[id.w];
        o4[j] = o;
    }
}

// ---------------------------------------------------------------------------
// Kernel 2: Jonker-Volgenant shortest augmenting path, one block per batch.
// Solves the transposed problem (rows = 128 targets, cols = 256 queries),
// exactly replicating scipy.optimize.linear_sum_assignment arithmetic (f64).
// Warp 0 does the solve; lanes own 8 columns each (j = lane + 32*k).
// ---------------------------------------------------------------------------
__global__ __launch_bounds__(256) void k_hungarian(
    const float* __restrict__ C,        // [BS*NQ, BT]
    float* __restrict__ rows_out,       // [BS*NT]
    float* __restrict__ cols_out)       // [BS*NT]
{
    extern __shared__ float cost[];     // [NT * NQ] transposed block (float)
    __shared__ double u[NT], v[NQ], dsh[NQ];
    __shared__ int path[NQ], row4col[NQ], col4row[NT];
    __shared__ unsigned char SR[NT];

    const int b = blockIdx.x;
    const int tid = threadIdx.x;

    // load + transpose the [NQ x NT] diagonal block into cost[t*NQ + q]
    {
        const float4* src = (const float4*)(C + ((size_t)(b * NQ + tid)) * BT + b * NT);
        #pragma unroll 4
        for (int t4 = 0; t4 < NT / 4; t4++) {
            float4 vv = src[t4];
            int t = t4 * 4;
            cost[(t + 0) * NQ + tid] = vv.x;
            cost[(t + 1) * NQ + tid] = vv.y;
            cost[(t + 2) * NQ + tid] = vv.z;
            cost[(t + 3) * NQ + tid] = vv.w;
        }
    }
    if (tid < NT) { u[tid] = 0.0; col4row[tid] = -1; SR[tid] = 0; }
    v[tid] = 0.0;
    row4col[tid] = -1;
    __syncthreads();

    if (tid >= 32) return;   // warp 0 only from here
    const int lane = tid;

    for (int cur = 0; cur < NT; cur++) {
        unsigned scmask = 0;  // SC bits for this lane's 8 columns
        #pragma unroll
        for (int k = 0; k < 8; k++) dsh[lane + 32 * k] = CUDART_INF;
        double minVal = 0.0;
        int i = cur;
        int sink = -1;
        __syncwarp();

        while (sink < 0) {
            if (lane == 0) SR[i] = 1;
            const double ui = u[i];
            const float* crow = cost + i * NQ;

            double bestv = CUDART_INF;
            int bestj = NQ;
            #pragma unroll
            for (int k = 0; k < 8; k++) {
                const int j = lane + 32 * k;
                if (!((scmask >> k) & 1u)) {
                    // r = minVal + cost[i,j] - u[i] - v[j]  (scipy order)
                    double r = minVal + (double)crow[j];
                    r = r - ui;
                    r = r - v[j];
                    double dj = dsh[j];
                    if (r < dj) { dj = r; dsh[j] = r; path[j] = i; }
                    if (dj < bestv) { bestv = dj; bestj = j; }
                }
            }
            // warp argmin, tie -> lowest column index
            #pragma unroll
            for (int o = 16; o; o >>= 1) {
                double ov = __shfl_xor_sync(0xffffffffu, bestv, o);
                int    oj = __shfl_xor_sync(0xffffffffu, bestj, o);
                if (ov < bestv || (ov == bestv && oj < bestj)) { bestv = ov; bestj = oj; }
            }
            minVal = bestv;
            if ((bestj & 31) == lane) scmask |= 1u << (bestj >> 5);
            __syncwarp();
            const int rj = row4col[bestj];
            if (rj < 0) sink = bestj;
            else i = rj;
            __syncwarp();
        }

        // dual updates (scipy order)
        if (lane == 0) u[cur] += minVal;
        __syncwarp();
        #pragma unroll
        for (int k = 0; k < 4; k++) {
            const int r = lane + 32 * k;
            if (SR[r]) {
                if (r != cur) u[r] += minVal - dsh[col4row[r]];
                SR[r] = 0;
            }
        }
        #pragma unroll
        for (int k = 0; k < 8; k++) {
            if ((scmask >> k) & 1u) {
                const int j = lane + 32 * k;
                v[j] -= (minVal - dsh[j]);
            }
        }
        __syncwarp();

        // augment along shortest path
        if (lane == 0) {
            int j = sink;
            while (true) {
                const int ii = path[j];
                row4col[j] = ii;
                const int jn = col4row[ii];
                col4row[ii] = j;
                j = jn;
                if (ii == cur) break;
            }
        }
        __syncwarp();
    }

    // emit: rows = sorted assigned queries, cols = corresponding targets
    #pragma unroll
    for (int k = 0; k < 4; k++) {
        const int t = lane + 32 * k;
        const int q = col4row[t];
        int rank = 0;
        for (int t2 = 0; t2 < NT; t2++) rank += (col4row[t2] < q) ? 1 : 0;
        rows_out[b * NT + rank] = (float)q;
        cols_out[b * NT + rank] = (float)t;
    }
}

// ---------------------------------------------------------------------------
extern "C" void kernel_launch(void* const* d_in, const int* in_sizes, int n_in,
                              void* d_out, int out_size)
{
    const float* logits = (const float*)d_in[0];   // [32,256,2048] f32
    const int*   tgt    = (const int*)d_in[1];     // [32,128] i32
    const int*   mask   = (const int*)d_in[2];     // [32,256] i32 (bool coerced)
    const int*   useBg  = (const int*)d_in[3];     // [1] i32

    float* out  = (float*)d_out;
    float* rows = out + CSIZE;
    float* cols = rows + (size_t)BS * NT;

    k_softmax_gather<<<BS * NQ, 256>>>(logits, tgt, mask, useBg, out);

    static bool attr_set = false;
    // idempotent attribute set (not a stream op; safe during graph capture)
    cudaFuncSetAttribute(k_hungarian, cudaFuncAttributeMaxDynamicSharedMemorySize,
                         NT * NQ * (int)sizeof(float));
    (void)attr_set;

    k_hungarian<<<BS, 256, NT * NQ * sizeof(float)>>>(out, rows, cols);
}

// round 2
// speedup vs baseline: 1.4006x; 1.4006x over previous
#include <cuda_runtime.h>
#include <math_constants.h>

#define BS 32
#define NQ 256
#define NT 128
#define NC 2048
#define BT (BS * NT)                  // 4096
#define CSIZE ((size_t)BS * NQ * BT)  // 33554432

// ---------------------------------------------------------------------------
// Sortable-integer mapping for IEEE f64 (no NaN / -0.0 in this algorithm):
// order of keys (unsigned) == order of doubles.
// ---------------------------------------------------------------------------
static __device__ __forceinline__ unsigned long long dkey(double x) {
    unsigned long long b = (unsigned long long)__double_as_longlong(x);
    return (b & 0x8000000000000000ULL) ? ~b : (b | 0x8000000000000000ULL);
}
static __device__ __forceinline__ double dunkey(unsigned long long k) {
    unsigned long long b = (k & 0x8000000000000000ULL) ? (k ^ 0x8000000000000000ULL) : ~k;
    return __longlong_as_double((long long)b);
}

// ---------------------------------------------------------------------------
// Kernel 1: masked softmax over classes + gather into cost matrix C = -prob
// One block per (b, q) row. 256 threads.  (unchanged from R1: ~36us)
// ---------------------------------------------------------------------------
__global__ __launch_bounds__(256) void k_softmax_gather(
    const float* __restrict__ logits,   // [BS*NQ, NC]
    const int*   __restrict__ tgt,      // [BT]
    const int*   __restrict__ mask,     // [BS*NQ] (0/1)
    const int*   __restrict__ useBg,    // [1]
    float*       __restrict__ out)      // [BS*NQ, BT]
{
    __shared__ float sh[NC];
    __shared__ int   st[BT];
    __shared__ float red[8];

    const int row = blockIdx.x;
    const int tid = threadIdx.x;
    const int lane = tid & 31;
    const int warp = tid >> 5;

    const bool active = (useBg[0] != 0) || (mask[row] != 0);
    float* orow = out + (size_t)row * BT;

    if (!active) {
        const float4 z = make_float4(-0.0f, -0.0f, -0.0f, -0.0f);
        float4* o4 = (float4*)orow;
        #pragma unroll
        for (int j = tid; j < BT / 4; j += 256) o4[j] = z;
        return;
    }

    {
        const int4* tg4 = (const int4*)tgt;
        int4* st4 = (int4*)st;
        for (int j = tid; j < BT / 4; j += 256) st4[j] = tg4[j];
    }

    const float4* l4 = (const float4*)(logits + (size_t)row * NC);
    float4 v0 = l4[tid];
    float4 v1 = l4[tid + 256];

    float m = fmaxf(fmaxf(fmaxf(v0.x, v0.y), fmaxf(v0.z, v0.w)),
                    fmaxf(fmaxf(v1.x, v1.y), fmaxf(v1.z, v1.w)));
    #pragma unroll
    for (int o = 16; o; o >>= 1) m = fmaxf(m, __shfl_xor_sync(0xffffffffu, m, o));
    if (lane == 0) red[warp] = m;
    __syncthreads();
    if (tid == 0) {
        float t = red[0];
        #pragma unroll
        for (int w = 1; w < 8; w++) t = fmaxf(t, red[w]);
        red[0] = t;
    }
    __syncthreads();
    m = red[0];
    __syncthreads();

    float4 e0, e1;
    e0.x = expf(v0.x - m); e0.y = expf(v0.y - m);
    e0.z = expf(v0.z - m); e0.w = expf(v0.w - m);
    e1.x = expf(v1.x - m); e1.y = expf(v1.y - m);
    e1.z = expf(v1.z - m); e1.w = expf(v1.w - m);
    float s = (e0.x + e0.y) + (e0.z + e0.w) + (e1.x + e1.y) + (e1.z + e1.w);
    #pragma unroll
    for (int o = 16; o; o >>= 1) s += __shfl_xor_sync(0xffffffffu, s, o);
    if (lane == 0) red[warp] = s;
    __syncthreads();
    if (tid == 0) {
        float t = red[0];
        #pragma unroll
        for (int w = 1; w < 8; w++) t += red[w];
        red[0] = t;
    }
    __syncthreads();
    const float S = red[0];

    float4 p0, p1;
    p0.x = e0.x / S; p0.y = e0.y / S; p0.z = e0.z / S; p0.w = e0.w / S;
    p1.x = e1.x / S; p1.y = e1.y / S; p1.z = e1.z / S; p1.w = e1.w / S;
    ((float4*)sh)[tid]       = p0;
    ((float4*)sh)[tid + 256] = p1;
    __syncthreads();

    float4* o4 = (float4*)orow;
    const int4* st4 = (const int4*)st;
    #pragma unroll
    for (int j = tid; j < BT / 4; j += 256) {
        int4 id = st4[j];
        float4 o;
        o.x = -sh[id.x];
        o.y = -sh[id.y];
        o.z = -sh[id.z];
        o.w = -sh[id.w];
        o4[j] = o;
    }
}

// ---------------------------------------------------------------------------
// Kernel 2: Jonker-Volgenant (scipy-exact f64 arithmetic), one block/batch.
// Transposed problem: rows = 128 targets, cols = 256 queries.
// Warp 0 solves; lane owns columns j = lane + 32k (k<8), with d/v/path
// register-resident and integer sortable-key comparisons + REDUX argmin.
// ---------------------------------------------------------------------------
__global__ __launch_bounds__(256) void k_hungarian(
    const float* __restrict__ C,        // [BS*NQ, BT]
    float* __restrict__ rows_out,       // [BS*NT]
    float* __restrict__ cols_out)       // [BS*NT]
{
    extern __shared__ float cost[];     // [NT * NQ] transposed block
    __shared__ double u[NT];
    __shared__ double dsh[NQ];          // mirror of d (for dual updates)
    __shared__ int path[NQ];
    __shared__ int row4col[NQ];
    __shared__ int col4row[NT];
    __shared__ unsigned char SR[NT];

    const int b = blockIdx.x;
    const int tid = threadIdx.x;

    // load + transpose [NQ x NT] diagonal block into cost[t*NQ + q]
    {
        const float4* src = (const float4*)(C + ((size_t)(b * NQ + tid)) * BT + b * NT);
        #pragma unroll
        for (int t4 = 0; t4 < NT / 4; t4++) {
            float4 vv = src[t4];
            int t = t4 * 4;
            cost[(t + 0) * NQ + tid] = vv.x;
            cost[(t + 1) * NQ + tid] = vv.y;
            cost[(t + 2) * NQ + tid] = vv.z;
            cost[(t + 3) * NQ + tid] = vv.w;
        }
    }
    if (tid < NT) { u[tid] = 0.0; col4row[tid] = -1; SR[tid] = 0; }
    row4col[tid] = -1;
    __syncthreads();

    if (tid >= 32) return;   // warp 0 only
    const int lane = tid;
    const unsigned FULL = 0xffffffffu;
    const unsigned long long KEYMAX = 0xFFFFFFFFFFFFFFFFULL;

    double vreg[8];
    #pragma unroll
    for (int k = 0; k < 8; k++) vreg[k] = 0.0;

    for (int cur = 0; cur < NT; cur++) {
        unsigned long long dk[8];
        #pragma unroll
        for (int k = 0; k < 8; k++) dk[k] = dkey(CUDART_INF);
        unsigned sc = 0;            // SC bits for lane's 8 columns
        double minVal = 0.0;
        int i = cur;
        int sink;

        while (true) {
            if (lane == 0) SR[i] = 1;
            const double ui = u[i];
            const float* crow = cost + i * NQ;
            float c[8];
            #pragma unroll
            for (int k = 0; k < 8; k++) c[k] = crow[lane + 32 * k];

            #pragma unroll
            for (int k = 0; k < 8; k++) {
                if (!(sc & (1u << k))) {
                    // scipy order: ((minVal + cost) - u) - v, all f64
                    double r = ((minVal + (double)c[k]) - ui) - vreg[k];
                    unsigned long long rk = dkey(r);
                    if (rk < dk[k]) {
                        dk[k] = rk;
                        dsh[lane + 32 * k] = r;
                        path[lane + 32 * k] = i;
                    }
                }
            }

            // lane-local argmin (ties -> lowest j, i.e. lowest k)
            unsigned long long K[8]; int J[8];
            #pragma unroll
            for (int k = 0; k < 8; k++) {
                K[k] = (sc & (1u << k)) ? KEYMAX : dk[k];
                J[k] = lane + 32 * k;
            }
            #pragma unroll
            for (int s = 1; s < 8; s <<= 1) {
                #pragma unroll
                for (int k = 0; k < 8; k += 2 * s) {
                    if (K[k + s] < K[k]) { K[k] = K[k + s]; J[k] = J[k + s]; }
                }
            }

            // warp argmin via 3x REDUX.SYNC on (hi32, lo32, j)
            unsigned hi = (unsigned)(K[0] >> 32);
            unsigned lo = (unsigned)K[0];
            unsigned mhi = __reduce_min_sync(FULL, hi);
            unsigned lo2 = (hi == mhi) ? lo : 0xFFFFFFFFu;
            unsigned mlo = __reduce_min_sync(FULL, lo2);
            unsigned jc  = (hi == mhi && lo == mlo) ? (unsigned)J[0] : 0xFFFFFFFFu;
            unsigned bestj = __reduce_min_sync(FULL, jc);

            int rj = row4col[bestj];                 // LDS broadcast (overlaps below)
            minVal = dunkey(((unsigned long long)mhi << 32) | mlo);
            if ((bestj & 31u) == (unsigned)lane) sc |= 1u << (bestj >> 5);
            if (rj < 0) { sink = (int)bestj; break; }
            i = rj;
        }
        __syncwarp();

        // dual updates (scipy order; all f64)
        if (lane == 0) u[cur] = u[cur] + minVal;
        #pragma unroll
        for (int k = 0; k < 4; k++) {
            const int r = lane + 32 * k;
            if (SR[r]) {
                if (r != cur) {
                    int j = col4row[r];
                    u[r] = u[r] + (minVal - dsh[j]);
                }
                SR[r] = 0;
            }
        }
        #pragma unroll
        for (int k = 0; k < 8; k++) {
            if (sc & (1u << k))
                vreg[k] = vreg[k] - (minVal - dunkey(dk[k]));
        }
        __syncwarp();

        // augment along shortest path
        if (lane == 0) {
            int j = sink;
            while (true) {
                const int ii = path[j];
                row4col[j] = ii;
                const int jn = col4row[ii];
                col4row[ii] = j;
                j = jn;
                if (ii == cur) break;
            }
        }
        __syncwarp();
    }

    // emit: rows = sorted assigned queries, cols = corresponding targets
    #pragma unroll
    for (int k = 0; k < 4; k++) {
        const int t = lane + 32 * k;
        const int q = col4row[t];
        int rank = 0;
        for (int t2 = 0; t2 < NT; t2++) rank += (col4row[t2] < q) ? 1 : 0;
        rows_out[b * NT + rank] = (float)q;
        cols_out[b * NT + rank] = (float)t;
    }
}

// ---------------------------------------------------------------------------
extern "C" void kernel_launch(void* const* d_in, const int* in_sizes, int n_in,
                              void* d_out, int out_size)
{
    const float* logits = (const float*)d_in[0];   // [32,256,2048] f32
    const int*   tgt    = (const int*)d_in[1];     // [32,128] i32
    const int*   mask   = (const int*)d_in[2];     // [32,256] i32
    const int*   useBg  = (const int*)d_in[3];     // [1] i32

    float* out  = (float*)d_out;
    float* rows = out + CSIZE;
    float* cols = rows + (size_t)BS * NT;

    k_softmax_gather<<<BS * NQ, 256>>>(logits, tgt, mask, useBg, out);

    cudaFuncSetAttribute(k_hungarian, cudaFuncAttributeMaxDynamicSharedMemorySize,
                         NT * NQ * (int)sizeof(float));
    k_hungarian<<<BS, 256, NT * NQ * sizeof(float)>>>(out, rows, cols);
}